// round 1
// baseline (speedup 1.0000x reference)
#include <cuda_runtime.h>

#define HID 128
#define NHEAD 8
#define HD 16
#define MAXN 50000
#define MAXE 500000

typedef unsigned long long ull;

// ---------------- static device scratch (no cudaMalloc allowed) ----------------
__device__ float g_q[MAXN * HID];
__device__ float g_k[MAXN * HID];
__device__ float g_v[MAXN * HID];
__device__ float g_xr[MAXN * HID];
__device__ float g_num[MAXN * HID];
__device__ float g_z[MAXN * NHEAD];
__device__ int   g_is64;

// ---------------- packed f32x2 helpers (sm_103a) ----------------
__device__ __forceinline__ ull ffma2(ull a, ull b, ull c) {
    ull d;
    asm("fma.rn.f32x2 %0, %1, %2, %3;" : "=l"(d) : "l"(a), "l"(b), "l"(c));
    return d;
}
__device__ __forceinline__ ull dup2(float x) {
    ull d;
    asm("mov.b64 %0, {%1, %1};" : "=l"(d) : "f"(x));
    return d;
}
__device__ __forceinline__ float2 unpack2(ull v) {
    float2 r;
    asm("mov.b64 {%0, %1}, %2;" : "=f"(r.x), "=f"(r.y) : "l"(v));
    return r;
}

// ---------------- index dtype probe: int64 vs (jax-downcast) int32 ----------------
__global__ void detect_kernel(const void* idx, long long total_elems) {
    if (threadIdx.x == 0 && blockIdx.x == 0) {
        const long long* p = (const long long*)idx;
        long long n = total_elems / 2;  // safe int64-element count either way
        if (n > 256) n = 256;
        int is64 = 1;
        for (long long i = 0; i < n; i++) {
            long long v = p[i];
            if (v < 0 || v >= (1LL << 31)) is64 = 0;
        }
        g_is64 = is64;
    }
}

__global__ void zero_kernel(int N) {
    int stride = gridDim.x * blockDim.x;
    int i = blockIdx.x * blockDim.x + threadIdx.x;
    int tot = N * HID;
    for (int k = i; k < tot; k += stride) g_num[k] = 0.f;
    int tz = N * NHEAD;
    for (int k = i; k < tz; k += stride) g_z[k] = 0.f;
}

// ---------------- shared GEMM tile core ----------------
// BM=64, BN=128, BK=8, 256 threads. acc holds 8x4 outputs per thread as
// 4x4 f32x2 pairs (pairs along M, contiguous in transposed A smem).
__device__ __forceinline__ void gemm_tile_core(
    const float* __restrict__ Arow, bool rowok,
    const float* __restrict__ W,
    float (*As)[68], float (*Bs)[128],
    int tid, int m0, int n0, int lr, int lc,
    ull acc[4][4])
{
    for (int k0 = 0; k0 < HID; k0 += 8) {
        float2 av = rowok ? *(const float2*)(Arow + k0 + lc) : make_float2(0.f, 0.f);
        As[lc][lr]     = av.x;
        As[lc + 1][lr] = av.y;
        float4 bv = *(const float4*)(W + (size_t)(k0 + (tid >> 5)) * HID + n0);
        *(float4*)&Bs[tid >> 5][n0] = bv;
        __syncthreads();
#pragma unroll
        for (int kk = 0; kk < 8; kk++) {
            const ull* ap = (const ull*)&As[kk][m0];
            ull a0 = ap[0], a1 = ap[1], a2 = ap[2], a3 = ap[3];
            float4 b = *(const float4*)&Bs[kk][n0];
            ull b0 = dup2(b.x), b1 = dup2(b.y), b2 = dup2(b.z), b3 = dup2(b.w);
            acc[0][0] = ffma2(a0, b0, acc[0][0]);
            acc[0][1] = ffma2(a0, b1, acc[0][1]);
            acc[0][2] = ffma2(a0, b2, acc[0][2]);
            acc[0][3] = ffma2(a0, b3, acc[0][3]);
            acc[1][0] = ffma2(a1, b0, acc[1][0]);
            acc[1][1] = ffma2(a1, b1, acc[1][1]);
            acc[1][2] = ffma2(a1, b2, acc[1][2]);
            acc[1][3] = ffma2(a1, b3, acc[1][3]);
            acc[2][0] = ffma2(a2, b0, acc[2][0]);
            acc[2][1] = ffma2(a2, b1, acc[2][1]);
            acc[2][2] = ffma2(a2, b2, acc[2][2]);
            acc[2][3] = ffma2(a2, b3, acc[2][3]);
            acc[3][0] = ffma2(a3, b0, acc[3][0]);
            acc[3][1] = ffma2(a3, b1, acc[3][1]);
            acc[3][2] = ffma2(a3, b2, acc[3][2]);
            acc[3][3] = ffma2(a3, b3, acc[3][3]);
        }
        __syncthreads();
    }
}

// ---------------- kernel A: node projections (X @ W + b) ----------------
__global__ __launch_bounds__(256) void node_gemm_kernel(
    const float* __restrict__ X, const float* __restrict__ W,
    const float* __restrict__ bias, float* __restrict__ out, int M)
{
    __shared__ __align__(16) float As[8][68];
    __shared__ __align__(16) float Bs[8][128];
    int tid = threadIdx.x;
    int mBase = blockIdx.x * 64;
    int m0 = (tid >> 5) * 8;
    int n0 = (tid & 31) * 4;
    int lr = tid >> 2;
    int lc = (tid & 3) * 2;

    ull acc[4][4];
#pragma unroll
    for (int r = 0; r < 4; r++)
#pragma unroll
        for (int c = 0; c < 4; c++) acc[r][c] = 0ULL;

    bool rowok = (mBase + lr) < M;
    const float* Arow = X + (size_t)(mBase + lr) * HID;
    gemm_tile_core(Arow, rowok, W, As, Bs, tid, m0, n0, lr, lc, acc);

#pragma unroll
    for (int r = 0; r < 4; r++) {
        int row0 = mBase + m0 + 2 * r;
#pragma unroll
        for (int c = 0; c < 4; c++) {
            float2 v = unpack2(acc[r][c]);
            float bb = bias[n0 + c];
            if (row0 < M)     out[(size_t)row0 * HID + n0 + c]       = v.x + bb;
            if (row0 + 1 < M) out[(size_t)(row0 + 1) * HID + n0 + c] = v.y + bb;
        }
    }
}

// ---------------- kernel B: fused edge GEMM + attention scatter ----------------
__global__ __launch_bounds__(256) void edge_kernel(
    const float* __restrict__ angle, const void* __restrict__ idx,
    const float* __restrict__ We, int E)
{
    __shared__ __align__(16) float As[8][68];
    __shared__ __align__(16) float Bs[8][128];
    __shared__ __align__(16) float es[64 * 132];  // e tile, padded rows

    int tid = threadIdx.x;
    int eBase = blockIdx.x * 64;
    int m0 = (tid >> 5) * 8;
    int n0 = (tid & 31) * 4;
    int lr = tid >> 2;
    int lc = (tid & 3) * 2;

    ull acc[4][4];
#pragma unroll
    for (int r = 0; r < 4; r++)
#pragma unroll
        for (int c = 0; c < 4; c++) acc[r][c] = 0ULL;

    bool rowok = (eBase + lr) < E;
    const float* Arow = angle + (size_t)(eBase + lr) * HID;
    gemm_tile_core(Arow, rowok, We, As, Bs, tid, m0, n0, lr, lc, acc);

    // stash e tile in smem
#pragma unroll
    for (int r = 0; r < 4; r++) {
        int row0 = m0 + 2 * r;
#pragma unroll
        for (int c = 0; c < 4; c++) {
            float2 v = unpack2(acc[r][c]);
            es[row0 * 132 + n0 + c]       = v.x;
            es[(row0 + 1) * 132 + n0 + c] = v.y;
        }
    }
    __syncthreads();

    // phase 2: 4 threads per edge, 2 heads per thread
    int j  = tid & 3;
    int el = tid >> 2;
    int eg = eBase + el;
    if (eg >= E) return;

    long long s, d;
    if (g_is64) {
        const long long* p = (const long long*)idx;
        s = p[eg];
        d = p[eg + E];
    } else {
        const int* p = (const int*)idx;
        s = p[eg];
        d = p[eg + E];
    }

    const float* qr = g_q + (size_t)d * HID;
    const float* kr = g_k + (size_t)s * HID;
    const float* vr = g_v + (size_t)s * HID;
    const float* er = es + el * 132;

    float a2[2];
#pragma unroll
    for (int hh = 0; hh < 2; hh++) {
        int base = (j * 2 + hh) * HD;
        float alpha = 0.f;
#pragma unroll
        for (int c = 0; c < 4; c++) {
            float4 q4 = *(const float4*)(qr + base + c * 4);
            float4 k4 = *(const float4*)(kr + base + c * 4);
            float4 e4 = *(const float4*)(er + base + c * 4);
            alpha += q4.x * (k4.x + e4.x) + q4.y * (k4.y + e4.y)
                   + q4.z * (k4.z + e4.z) + q4.w * (k4.w + e4.w);
        }
        // softmax without max-shift: alpha/4 is bounded (~|8| worst case), exp safe
        a2[hh] = __expf(alpha * 0.25f);
    }

    asm volatile("red.global.add.v2.f32 [%0], {%1, %2};"
                 :: "l"(g_z + (size_t)d * NHEAD + j * 2), "f"(a2[0]), "f"(a2[1])
                 : "memory");

    float* nr = g_num + (size_t)d * HID;
#pragma unroll
    for (int hh = 0; hh < 2; hh++) {
        int base = (j * 2 + hh) * HD;
        float a = a2[hh];
#pragma unroll
        for (int c = 0; c < 4; c++) {
            float4 v4 = *(const float4*)(vr + base + c * 4);
            float4 e4 = *(const float4*)(er + base + c * 4);
            float rx = a * (v4.x + e4.x);
            float ry = a * (v4.y + e4.y);
            float rz = a * (v4.z + e4.z);
            float rw = a * (v4.w + e4.w);
            asm volatile("red.global.add.v4.f32 [%0], {%1, %2, %3, %4};"
                         :: "l"(nr + base + c * 4), "f"(rx), "f"(ry), "f"(rz), "f"(rw)
                         : "memory");
        }
    }
}

// ---------------- kernel C: finalize (softmax div, beta gate, LN, relu, residual) ----------------
__global__ __launch_bounds__(256) void finalize_kernel(
    const float* __restrict__ x, const float* __restrict__ Wbeta,
    const float* __restrict__ gamma, const float* __restrict__ lbeta,
    float* __restrict__ out, int N)
{
    int warp = threadIdx.x >> 5;
    int lane = threadIdx.x & 31;
    int n = blockIdx.x * 8 + warp;
    if (n >= N) return;
    int c = lane * 4;

    float4 num = *(const float4*)(g_num + (size_t)n * HID + c);
    float z = g_z[(size_t)n * NHEAD + (lane >> 2)];
    float inv = z > 0.f ? 1.f / z : 0.f;
    float4 o = make_float4(num.x * inv, num.y * inv, num.z * inv, num.w * inv);
    float4 xr = *(const float4*)(g_xr + (size_t)n * HID + c);

    float4 wb0 = *(const float4*)(Wbeta + c);
    float4 wb1 = *(const float4*)(Wbeta + 128 + c);
    float4 wb2 = *(const float4*)(Wbeta + 256 + c);
    float dot = o.x * wb0.x + o.y * wb0.y + o.z * wb0.z + o.w * wb0.w
              + xr.x * wb1.x + xr.y * wb1.y + xr.z * wb1.z + xr.w * wb1.w
              + (o.x - xr.x) * wb2.x + (o.y - xr.y) * wb2.y
              + (o.z - xr.z) * wb2.z + (o.w - xr.w) * wb2.w;
#pragma unroll
    for (int m = 16; m; m >>= 1) dot += __shfl_xor_sync(0xffffffffu, dot, m);
    float beta = 1.f / (1.f + __expf(-dot));

    float4 g;
    g.x = beta * xr.x + (1.f - beta) * o.x;
    g.y = beta * xr.y + (1.f - beta) * o.y;
    g.z = beta * xr.z + (1.f - beta) * o.z;
    g.w = beta * xr.w + (1.f - beta) * o.w;

    float s = g.x + g.y + g.z + g.w;
#pragma unroll
    for (int m = 16; m; m >>= 1) s += __shfl_xor_sync(0xffffffffu, s, m);
    float mu = s * (1.f / 128.f);

    float dx = g.x - mu, dy = g.y - mu, dz = g.z - mu, dw = g.w - mu;
    float vs = dx * dx + dy * dy + dz * dz + dw * dw;
#pragma unroll
    for (int m = 16; m; m >>= 1) vs += __shfl_xor_sync(0xffffffffu, vs, m);
    float rstd = rsqrtf(vs * (1.f / 128.f) + 1e-5f);

    float4 gm = *(const float4*)(gamma + c);
    float4 lb = *(const float4*)(lbeta + c);
    float4 xin = *(const float4*)(x + (size_t)n * HID + c);

    float4 res;
    float y;
    y = dx * rstd * gm.x + lb.x; res.x = xin.x + fmaxf(y, 0.f);
    y = dy * rstd * gm.y + lb.y; res.y = xin.y + fmaxf(y, 0.f);
    y = dz * rstd * gm.z + lb.z; res.z = xin.z + fmaxf(y, 0.f);
    y = dw * rstd * gm.w + lb.w; res.w = xin.w + fmaxf(y, 0.f);
    *(float4*)(out + (size_t)n * HID + c) = res;
}

// ---------------- launch ----------------
extern "C" void kernel_launch(void* const* d_in, const int* in_sizes, int n_in,
                              void* d_out, int out_size)
{
    const float* edge_state = (const float*)d_in[0];
    const void*  idx        = d_in[1];
    const float* angle      = (const float*)d_in[2];
    const float* Wq = (const float*)d_in[3];
    const float* bq = (const float*)d_in[4];
    const float* Wk = (const float*)d_in[5];
    const float* bk = (const float*)d_in[6];
    const float* Wv = (const float*)d_in[7];
    const float* bv = (const float*)d_in[8];
    const float* We = (const float*)d_in[9];
    const float* Ws = (const float*)d_in[10];
    const float* bs = (const float*)d_in[11];
    const float* Wbeta = (const float*)d_in[12];
    const float* gamma = (const float*)d_in[13];
    const float* lbeta = (const float*)d_in[14];

    int N = in_sizes[0] / HID;
    int E = in_sizes[2] / HID;

    float *pq, *pk, *pv, *pxr;
    cudaGetSymbolAddress((void**)&pq, g_q);
    cudaGetSymbolAddress((void**)&pk, g_k);
    cudaGetSymbolAddress((void**)&pv, g_v);
    cudaGetSymbolAddress((void**)&pxr, g_xr);

    detect_kernel<<<1, 32>>>(idx, (long long)in_sizes[1]);
    zero_kernel<<<512, 256>>>(N);

    dim3 gA((N + 63) / 64);
    node_gemm_kernel<<<gA, 256>>>(edge_state, Wq, bq, pq, N);
    node_gemm_kernel<<<gA, 256>>>(edge_state, Wk, bk, pk, N);
    node_gemm_kernel<<<gA, 256>>>(edge_state, Wv, bv, pv, N);
    node_gemm_kernel<<<gA, 256>>>(edge_state, Ws, bs, pxr, N);

    edge_kernel<<<(E + 63) / 64, 256>>>(angle, idx, We, E);

    finalize_kernel<<<(N + 7) / 8, 256>>>(edge_state, Wbeta, gamma, lbeta,
                                          (float*)d_out, N);
}